// round 12
// baseline (speedup 1.0000x reference)
#include <cuda_runtime.h>
#include <math.h>

#define PNT 20
#define KNN 8
#define D0  128
#define MAXN 8192
typedef unsigned long long ull;

__device__ float g_act[ (size_t)MAXN*PNT*512 ];   // activations (widest 512)
__device__ float g_tmp[ (size_t)MAXN*PNT*512 ];   // xagg scratch (widest 512)

__device__ __forceinline__ ull pack2f(float x, float y){
    return ((ull)__float_as_uint(y) << 32) | (ull)__float_as_uint(x);
}
__device__ __forceinline__ ull ffma2(ull a, ull b, ull c){
    ull d;
    asm("fma.rn.f32x2 %0, %1, %2, %3;" : "=l"(d) : "l"(a), "l"(b), "l"(c));
    return d;
}
__device__ __forceinline__ float lo2(ull v){ return __uint_as_float((unsigned)(v & 0xffffffffull)); }
__device__ __forceinline__ float hi2(ull v){ return __uint_as_float((unsigned)(v >> 32)); }
__device__ __forceinline__ float warp_sum(float v){
    #pragma unroll
    for(int m=16;m>0;m>>=1) v += __shfl_xor_sync(0xffffffffu, v, m);
    return v;
}

// ============================================================================
// sgemm: C[M,N] = A[M,K] @ B[K,N] (+bias+relu if EPI). 128x128x16 tiles,
// double buffered, dynamic smem. Warp tiling: 8 warps = 4(m) x 2(n),
// lanes 4(m) x 8(n). B stored PRE-DUPLICATED as (b,b) ulls so the inner
// loop is 6 LDS.128 + 32 ffma2 (pack cost amortized 16x into the loader).
// ============================================================================
#define AS_PITCH 132
template<bool EPI>
__global__ void __launch_bounds__(256,2)
sgemm_kernel(const float* __restrict__ A, const float* __restrict__ B,
             const float* __restrict__ bias, float* __restrict__ C,
             int M, int N, int K)
{
    extern __shared__ __align__(16) char smem_raw[];
    float* As = (float*)smem_raw;                      // [2][16][AS_PITCH]
    ull*   Bs = (ull*)(smem_raw + 2*16*AS_PITCH*4);    // [2][16][128] duplicated
    #define AS(b,k,m) As[((b)*16 + (k))*AS_PITCH + (m)]
    #define BS(b,k,n) Bs[((b)*16 + (k))*128 + (n)]

    const int tid = threadIdx.x;
    const int warp = tid >> 5, lane = tid & 31;
    const int wm = warp >> 1, wn = warp & 1;         // warp grid 4(m) x 2(n)
    const int lm = lane & 3,  ln = lane >> 2;        // lane grid 4(m) x 8(n)
    const int m0 = blockIdx.y * 128, n0 = blockIdx.x * 128;
    const int ar = tid >> 2, ac = (tid & 3) * 4;     // A loader: rows ar, ar+64
    const int br = tid >> 5, bc = (tid & 31) * 4;    // B loader: rows br, br+8

    const float* Ag = A + (long long)(m0 + ar) * K + ac;
    const float* Bg = B + (long long)br * N + (n0 + bc);

    {
        float4 a0 = *(const float4*)(Ag);
        float4 a1 = *(const float4*)(Ag + (long long)64 * K);
        float4 b0 = *(const float4*)(Bg);
        float4 b1 = *(const float4*)(Bg + (long long)8 * N);
        AS(0,ac+0,ar) = a0.x; AS(0,ac+1,ar) = a0.y;
        AS(0,ac+2,ar) = a0.z; AS(0,ac+3,ar) = a0.w;
        AS(0,ac+0,ar+64) = a1.x; AS(0,ac+1,ar+64) = a1.y;
        AS(0,ac+2,ar+64) = a1.z; AS(0,ac+3,ar+64) = a1.w;
        *(ulonglong2*)&BS(0,br,bc)    = make_ulonglong2(pack2f(b0.x,b0.x), pack2f(b0.y,b0.y));
        *(ulonglong2*)&BS(0,br,bc+2)  = make_ulonglong2(pack2f(b0.z,b0.z), pack2f(b0.w,b0.w));
        *(ulonglong2*)&BS(0,br+8,bc)  = make_ulonglong2(pack2f(b1.x,b1.x), pack2f(b1.y,b1.y));
        *(ulonglong2*)&BS(0,br+8,bc+2)= make_ulonglong2(pack2f(b1.z,b1.z), pack2f(b1.w,b1.w));
    }
    __syncthreads();

    ull acc[4][8];
    #pragma unroll
    for(int r=0;r<4;r++){
        #pragma unroll
        for(int c=0;c<8;c++) acc[r][c]=0ull;
    }

    const int mb = wm*32 + lm*4;
    const int nb = wn*64 + ln*4;

    const int nk = K >> 4;
    for(int t=0;t<nk;t++){
        const int cur = t & 1;
        float4 na0,na1,nb0,nb1;
        if(t+1<nk){
            const float* Ag2 = Ag + (t+1)*16;
            const float* Bg2 = Bg + (long long)((t+1)*16) * N;
            na0 = *(const float4*)(Ag2);
            na1 = *(const float4*)(Ag2 + (long long)64 * K);
            nb0 = *(const float4*)(Bg2);
            nb1 = *(const float4*)(Bg2 + (long long)8 * N);
        }
        #pragma unroll
        for(int k=0;k<16;k++){
            ulonglong2 a01 = *(const ulonglong2*)&AS(cur,k,mb);
            ulonglong2 a23 = *(const ulonglong2*)&AS(cur,k,mb+16);
            ulonglong2 w01 = *(const ulonglong2*)&BS(cur,k,nb);
            ulonglong2 w23 = *(const ulonglong2*)&BS(cur,k,nb+2);
            ulonglong2 w45 = *(const ulonglong2*)&BS(cur,k,nb+32);
            ulonglong2 w67 = *(const ulonglong2*)&BS(cur,k,nb+34);
            ull am[4] = {a01.x, a01.y, a23.x, a23.y};
            ull ww[8] = {w01.x,w01.y,w23.x,w23.y,w45.x,w45.y,w67.x,w67.y};
            #pragma unroll
            for(int c=0;c<8;c++){
                #pragma unroll
                for(int r=0;r<4;r++) acc[r][c] = ffma2(am[r], ww[c], acc[r][c]);
            }
        }
        if(t+1<nk){
            const int nxt = cur ^ 1;
            AS(nxt,ac+0,ar) = na0.x; AS(nxt,ac+1,ar) = na0.y;
            AS(nxt,ac+2,ar) = na0.z; AS(nxt,ac+3,ar) = na0.w;
            AS(nxt,ac+0,ar+64) = na1.x; AS(nxt,ac+1,ar+64) = na1.y;
            AS(nxt,ac+2,ar+64) = na1.z; AS(nxt,ac+3,ar+64) = na1.w;
            *(ulonglong2*)&BS(nxt,br,bc)    = make_ulonglong2(pack2f(nb0.x,nb0.x), pack2f(nb0.y,nb0.y));
            *(ulonglong2*)&BS(nxt,br,bc+2)  = make_ulonglong2(pack2f(nb0.z,nb0.z), pack2f(nb0.w,nb0.w));
            *(ulonglong2*)&BS(nxt,br+8,bc)  = make_ulonglong2(pack2f(nb1.x,nb1.x), pack2f(nb1.y,nb1.y));
            *(ulonglong2*)&BS(nxt,br+8,bc+2)= make_ulonglong2(pack2f(nb1.z,nb1.z), pack2f(nb1.w,nb1.w));
        }
        __syncthreads();
    }

    float bz[8];
    if(EPI){
        float4 q0 = *(const float4*)(bias + n0 + nb);
        float4 q1 = *(const float4*)(bias + n0 + nb + 32);
        bz[0]=q0.x; bz[1]=q0.y; bz[2]=q0.z; bz[3]=q0.w;
        bz[4]=q1.x; bz[5]=q1.y; bz[6]=q1.z; bz[7]=q1.w;
    }
    #pragma unroll
    for(int r=0;r<4;r++){
        const int row_lo = m0 + mb + (r&1)*2 + (r>>1)*16;
        float vl[8], vh[8];
        #pragma unroll
        for(int c=0;c<8;c++){
            float lo = lo2(acc[r][c]), hi = hi2(acc[r][c]);
            if(EPI){ lo = fmaxf(lo + bz[c], 0.f); hi = fmaxf(hi + bz[c], 0.f); }
            vl[c]=lo; vh[c]=hi;
        }
        float* c0 = C + (long long)(row_lo    ) * N + n0 + nb;
        float* c1 = C + (long long)(row_lo + 1) * N + n0 + nb;
        *(float4*)(c0)    = make_float4(vl[0],vl[1],vl[2],vl[3]);
        *(float4*)(c0+32) = make_float4(vl[4],vl[5],vl[6],vl[7]);
        *(float4*)(c1)    = make_float4(vh[0],vh[1],vh[2],vh[3]);
        *(float4*)(c1+32) = make_float4(vh[4],vh[5],vh[6],vh[7]);
    }
    #undef AS
    #undef BS
}
#define SGEMM_SMEM (2*16*AS_PITCH*4 + 2*16*128*8)

// ============================================================================
// graph kernel: Gram (ffma2) -> kNN -> packed NmP (overlaid on G's smem)
// -> Xagg = Nm @ Ap  (aggregate-before).  (UNCHANGED from R11.)
// ============================================================================
template<int IN>
__global__ void __launch_bounds__(256)
graph_kernel(const float* __restrict__ act, float* __restrict__ outp)
{
    __shared__ __align__(16) float Ap[PNT*IN];   // points-major: Ap[p*IN + f]
    __shared__ __align__(16) ull   buf[PNT*PNT]; // G (float) then NmP (ull)
    __shared__ unsigned char pii[210], pjj[210];
    __shared__ int   knn[PNT*KNN];
    __shared__ int   deg[PNT];
    __shared__ float dinv[PNT];

    float* G   = (float*)buf;
    ull*   NmP = buf;

    const int tid = threadIdx.x, warp = tid >> 5, lane = tid & 31;
    const long long b = blockIdx.x;

    if(tid < 210){
        int i=0, rem=tid;
        while(rem >= PNT-i){ rem -= PNT-i; i++; }
        pii[tid]=(unsigned char)i; pjj[tid]=(unsigned char)(i+rem);
    }
    {
        const float4* src4 = (const float4*)(act + b*(long long)(PNT*IN));
        float4* Ap4 = (float4*)Ap;
        for(int q=tid;q<PNT*IN/4;q+=256) Ap4[q]=src4[q];
    }
    if(tid<PNT) deg[tid]=1;      // self loop
    __syncthreads();

    for(int q0 = warp*4; q0 < 210; q0 += 32){
        int ii[4], jj[4]; float accv[4];
        #pragma unroll
        for(int u=0;u<4;u++){
            int q = q0+u; if(q >= 210) q = 0;
            ii[u]=pii[q]; jj[u]=pjj[q];
        }
        #pragma unroll
        for(int u=0;u<4;u++){
            const ulonglong2* ri = (const ulonglong2*)&Ap[ii[u]*IN];
            const ulonglong2* rj = (const ulonglong2*)&Ap[jj[u]*IN];
            ull s0=0ull, s1=0ull;
            #pragma unroll
            for(int c=0;c<IN/128;c++){
                ulonglong2 av = ri[lane + c*32], bv = rj[lane + c*32];
                s0 = ffma2(av.x, bv.x, s0);
                s1 = ffma2(av.y, bv.y, s1);
            }
            accv[u] = (lo2(s0)+hi2(s0)) + (lo2(s1)+hi2(s1));
        }
        #pragma unroll
        for(int u=0;u<4;u++) accv[u]=warp_sum(accv[u]);
        if(lane==0){
            #pragma unroll
            for(int u=0;u<4;u++) if(q0+u<210){
                G[ii[u]*PNT+jj[u]] = accv[u];
                G[jj[u]*PNT+ii[u]] = accv[u];
            }
        }
    }
    __syncthreads();

    // stable K-smallest per row from G (exact reference d2 formula)
    if(tid<PNT){
        const int i = tid;
        const float gii = G[i*PNT+i];
        float row[PNT];
        #pragma unroll
        for(int j=0;j<PNT;j++)
            row[j] = (j==i) ? __int_as_float(0xff800000)
                            : gii + G[j*PNT+j] - 2.f*G[i*PNT+j];
        unsigned used=0;
        #pragma unroll
        for(int k=0;k<KNN+1;k++){
            float best = __int_as_float(0x7f800000); int bj=0;
            #pragma unroll
            for(int j=0;j<PNT;j++){
                if( !((used>>j)&1u) && row[j] < best ){ best=row[j]; bj=j; }
            }
            used |= 1u<<bj;
            if(k>0) knn[tid*KNN + (k-1)] = bj;
        }
    }
    __syncthreads();                               // G dead; buf becomes NmP

    if(tid<PNT*KNN) atomicAdd(&deg[knn[tid]], 1);
    for(int q=tid;q<PNT*PNT;q+=256) NmP[q]=0ull;
    __syncthreads();
    if(tid<PNT) dinv[tid] = rsqrtf((float)deg[tid]);
    __syncthreads();
    if(tid<PNT*KNN){
        int u = tid>>3;
        int t = knn[tid];
        float w = dinv[t]*dinv[u];
        NmP[u*PNT+t] = pack2f(w,w);
    }
    if(tid<PNT){ float w = dinv[tid]*dinv[tid]; NmP[tid*PNT+tid] = pack2f(w,w); }
    __syncthreads();

    for(int f2 = tid; 2*f2 < IN; f2 += 256){
        ull acc[PNT];
        #pragma unroll
        for(int t=0;t<PNT;t++) acc[t]=0ull;
        #pragma unroll 2
        for(int s=0;s<PNT;s++){
            ull av = *(const ull*)&Ap[s*IN + 2*f2];
            const ull* nrow = &NmP[s*PNT];
            #pragma unroll
            for(int t=0;t<PNT;t++) acc[t] = ffma2(av, nrow[t], acc[t]);
        }
        float* dst = outp + b*(long long)(PNT*IN);
        #pragma unroll
        for(int t=0;t<PNT;t++) *(ull*)&dst[t*IN + 2*f2] = acc[t];
    }
}

// ============================================================================
// head: mean pool -> fc 128x64 relu -> fc 64x3 -> softmax
// ============================================================================
__global__ void __launch_bounds__(128)
head_kernel(const float* __restrict__ act,
            const float* __restrict__ W4, const float* __restrict__ b4,
            const float* __restrict__ W5, const float* __restrict__ b5,
            float* __restrict__ out)
{
    __shared__ float msm[128], hsm[64], lsm[3];
    const int tid = threadIdx.x;
    const long long b = blockIdx.x;
    const float* ab = act + b*(long long)(PNT*128);
    {
        float s=0.f;
        #pragma unroll
        for(int p=0;p<PNT;p++) s += ab[p*128 + tid];
        msm[tid] = s * (1.f/PNT);
    }
    __syncthreads();
    if(tid<64){
        float a=b4[tid];
        #pragma unroll 4
        for(int f=0;f<128;f++) a = fmaf(msm[f], W4[f*64+tid], a);
        hsm[tid]=fmaxf(a,0.f);
    }
    __syncthreads();
    if(tid<3){
        float a=b5[tid];
        #pragma unroll
        for(int j=0;j<64;j++) a = fmaf(hsm[j], W5[j*3+tid], a);
        lsm[tid]=a;
    }
    __syncthreads();
    if(tid==0){
        float l0=lsm[0], l1=lsm[1], l2=lsm[2];
        float m=fmaxf(l0,fmaxf(l1,l2));
        float e0=expf(l0-m), e1=expf(l1-m), e2=expf(l2-m);
        float s=e0+e1+e2;
        out[b*3+0]=e0/s; out[b*3+1]=e1/s; out[b*3+2]=e2/s;
    }
}

extern "C" void kernel_launch(void* const* d_in, const int* in_sizes, int n_in,
                              void* d_out, int out_size){
    const float* x  = (const float*)d_in[0];
    const float* W1 = (const float*)d_in[1];
    const float* b1 = (const float*)d_in[2];
    const float* W2 = (const float*)d_in[3];
    const float* b2 = (const float*)d_in[4];
    const float* W3 = (const float*)d_in[5];
    const float* b3 = (const float*)d_in[6];
    const float* W4 = (const float*)d_in[7];
    const float* b4 = (const float*)d_in[8];
    const float* W5 = (const float*)d_in[9];
    const float* b5 = (const float*)d_in[10];
    float* out = (float*)d_out;

    const int NS = in_sizes[0]/(PNT*D0);   // 8192
    const int M  = NS*PNT;                 // 163840

    float *act, *tmp;
    cudaGetSymbolAddress((void**)&act, g_act);
    cudaGetSymbolAddress((void**)&tmp, g_tmp);

    cudaFuncSetAttribute(sgemm_kernel<true>,
        cudaFuncAttributeMaxDynamicSharedMemorySize, SGEMM_SMEM);

    // layer 1: xagg = Nm@x, then GEMM+bias+relu (aggregate-before)
    graph_kernel<128><<<NS,256>>>(x, tmp);
    sgemm_kernel<true><<<dim3(2, M/128),256,SGEMM_SMEM>>>(tmp, W1, b1, act, M, 256, 128);
    // layer 2
    graph_kernel<256><<<NS,256>>>(act, tmp);
    sgemm_kernel<true><<<dim3(4, M/128),256,SGEMM_SMEM>>>(tmp, W2, b2, act, M, 512, 256);
    // layer 3
    graph_kernel<512><<<NS,256>>>(act, tmp);
    sgemm_kernel<true><<<dim3(1, M/128),256,SGEMM_SMEM>>>(tmp, W3, b3, act, M, 128, 512);
    // head
    head_kernel<<<NS,128>>>(act, W4, b4, W5, b5, out);
}

// round 13
// speedup vs baseline: 1.0901x; 1.0901x over previous
#include <cuda_runtime.h>
#include <math.h>

#define PNT 20
#define KNN 8
#define D0  128
#define MAXN 8192
typedef unsigned long long ull;

__device__ float g_act[ (size_t)MAXN*PNT*512 ];   // activations (widest 512)
__device__ float g_tmp[ (size_t)MAXN*PNT*512 ];   // xagg scratch (widest 512)

__device__ __forceinline__ ull pack2f(float x, float y){
    return ((ull)__float_as_uint(y) << 32) | (ull)__float_as_uint(x);
}
__device__ __forceinline__ ull ffma2(ull a, ull b, ull c){
    ull d;
    asm("fma.rn.f32x2 %0, %1, %2, %3;" : "=l"(d) : "l"(a), "l"(b), "l"(c));
    return d;
}
__device__ __forceinline__ float lo2(ull v){ return __uint_as_float((unsigned)(v & 0xffffffffull)); }
__device__ __forceinline__ float hi2(ull v){ return __uint_as_float((unsigned)(v >> 32)); }
__device__ __forceinline__ float warp_sum(float v){
    #pragma unroll
    for(int m=16;m>0;m>>=1) v += __shfl_xor_sync(0xffffffffu, v, m);
    return v;
}

// ============================================================================
// sgemm: EXACT R11 version (proven: fma 69.1%, 787us on L2 shape).
// 128x128x16 tiles, double buffered, static smem. 8 warps = 4(m) x 2(n),
// lanes 4(m) x 8(n). A as natural (m,m+1) ull pairs; B float4 + in-loop pack.
// ============================================================================
template<bool EPI>
__global__ void __launch_bounds__(256,2)
sgemm_kernel(const float* __restrict__ A, const float* __restrict__ B,
             const float* __restrict__ bias, float* __restrict__ C,
             int M, int N, int K)
{
    __shared__ __align__(16) float As[2][16][132];   // transposed + pad: As[k][m]
    __shared__ __align__(16) float Bs[2][16][128];   // Bs[k][n]
    const int tid = threadIdx.x;
    const int warp = tid >> 5, lane = tid & 31;
    const int wm = warp >> 1, wn = warp & 1;
    const int lm = lane & 3,  ln = lane >> 2;
    const int m0 = blockIdx.y * 128, n0 = blockIdx.x * 128;
    const int ar = tid >> 2, ac = (tid & 3) * 4;
    const int br = tid >> 5, bc = (tid & 31) * 4;

    const float* Ag = A + (long long)(m0 + ar) * K + ac;
    const float* Bg = B + (long long)br * N + (n0 + bc);

    {
        float4 a0 = *(const float4*)(Ag);
        float4 a1 = *(const float4*)(Ag + (long long)64 * K);
        float4 b0 = *(const float4*)(Bg);
        float4 b1 = *(const float4*)(Bg + (long long)8 * N);
        As[0][ac+0][ar] = a0.x; As[0][ac+1][ar] = a0.y;
        As[0][ac+2][ar] = a0.z; As[0][ac+3][ar] = a0.w;
        As[0][ac+0][ar+64] = a1.x; As[0][ac+1][ar+64] = a1.y;
        As[0][ac+2][ar+64] = a1.z; As[0][ac+3][ar+64] = a1.w;
        *(float4*)&Bs[0][br  ][bc] = b0;
        *(float4*)&Bs[0][br+8][bc] = b1;
    }
    __syncthreads();

    ull acc[4][8];
    #pragma unroll
    for(int r=0;r<4;r++){
        #pragma unroll
        for(int c=0;c<8;c++) acc[r][c]=0ull;
    }

    const int mb = wm*32 + lm*4;
    const int nb = wn*64 + ln*4;

    const int nk = K >> 4;
    for(int t=0;t<nk;t++){
        const int cur = t & 1;
        float4 na0,na1,nb0,nb1;
        if(t+1<nk){
            const float* Ag2 = Ag + (t+1)*16;
            const float* Bg2 = Bg + (long long)((t+1)*16) * N;
            na0 = *(const float4*)(Ag2);
            na1 = *(const float4*)(Ag2 + (long long)64 * K);
            nb0 = *(const float4*)(Bg2);
            nb1 = *(const float4*)(Bg2 + (long long)8 * N);
        }
        #pragma unroll
        for(int k=0;k<16;k++){
            ulonglong2 a01 = *(const ulonglong2*)&As[cur][k][mb];
            ulonglong2 a23 = *(const ulonglong2*)&As[cur][k][mb+16];
            float4 q0 = *(const float4*)&Bs[cur][k][nb];
            float4 q1 = *(const float4*)&Bs[cur][k][nb+32];
            ull am[4] = {a01.x, a01.y, a23.x, a23.y};
            float bb[8] = {q0.x,q0.y,q0.z,q0.w, q1.x,q1.y,q1.z,q1.w};
            #pragma unroll
            for(int c=0;c<8;c++){
                ull w = pack2f(bb[c], bb[c]);
                #pragma unroll
                for(int r=0;r<4;r++) acc[r][c] = ffma2(am[r], w, acc[r][c]);
            }
        }
        if(t+1<nk){
            const int nxt = cur ^ 1;
            As[nxt][ac+0][ar] = na0.x; As[nxt][ac+1][ar] = na0.y;
            As[nxt][ac+2][ar] = na0.z; As[nxt][ac+3][ar] = na0.w;
            As[nxt][ac+0][ar+64] = na1.x; As[nxt][ac+1][ar+64] = na1.y;
            As[nxt][ac+2][ar+64] = na1.z; As[nxt][ac+3][ar+64] = na1.w;
            *(float4*)&Bs[nxt][br  ][bc] = nb0;
            *(float4*)&Bs[nxt][br+8][bc] = nb1;
        }
        __syncthreads();
    }

    float bz[8];
    if(EPI){
        float4 q0 = *(const float4*)(bias + n0 + nb);
        float4 q1 = *(const float4*)(bias + n0 + nb + 32);
        bz[0]=q0.x; bz[1]=q0.y; bz[2]=q0.z; bz[3]=q0.w;
        bz[4]=q1.x; bz[5]=q1.y; bz[6]=q1.z; bz[7]=q1.w;
    }
    #pragma unroll
    for(int r=0;r<4;r++){
        const int row_lo = m0 + mb + (r&1)*2 + (r>>1)*16;
        float vl[8], vh[8];
        #pragma unroll
        for(int c=0;c<8;c++){
            float lo = lo2(acc[r][c]), hi = hi2(acc[r][c]);
            if(EPI){ lo = fmaxf(lo + bz[c], 0.f); hi = fmaxf(hi + bz[c], 0.f); }
            vl[c]=lo; vh[c]=hi;
        }
        float* c0 = C + (long long)(row_lo    ) * N + n0 + nb;
        float* c1 = C + (long long)(row_lo + 1) * N + n0 + nb;
        *(float4*)(c0)    = make_float4(vl[0],vl[1],vl[2],vl[3]);
        *(float4*)(c0+32) = make_float4(vl[4],vl[5],vl[6],vl[7]);
        *(float4*)(c1)    = make_float4(vh[0],vh[1],vh[2],vh[3]);
        *(float4*)(c1+32) = make_float4(vh[4],vh[5],vh[6],vh[7]);
    }
}

// ============================================================================
// graph kernel, batched: B samples per CTA (B*IN/2 == 512-lane Xagg fill).
// Per sample: Gram (ffma2) -> kNN select -> packed NmP (overlays G) ->
// Xagg = Nm @ Ap. Dynamic smem, manual layout.
// ============================================================================
template<int IN, int NB>
__global__ void __launch_bounds__(256)
graph_kernel(const float* __restrict__ act, float* __restrict__ outp)
{
    extern __shared__ __align__(16) char gsm[];
    // layout (AP always 40960 bytes since NB*IN = 512)
    float*          Ap   = (float*)gsm;                          // NB * PNT*IN
    ull*            bufA = (ull*)(gsm + 40960);                  // NB * PNT*PNT (G/NmP)
    unsigned char*  knn  = (unsigned char*)(gsm + 40960 + NB*PNT*PNT*8);
    int*            deg  = (int*)(knn + NB*PNT*KNN);
    float*          dinv = (float*)(deg + NB*PNT);
    unsigned char*  pii  = (unsigned char*)(dinv + NB*PNT);
    unsigned char*  pjj  = pii + 210;

    const int tid = threadIdx.x, warp = tid >> 5, lane = tid & 31;
    const long long b0 = (long long)blockIdx.x * NB;

    if(tid < 210){
        int i=0, rem=tid;
        while(rem >= PNT-i){ rem -= PNT-i; i++; }
        pii[tid]=(unsigned char)i; pjj[tid]=(unsigned char)(i+rem);
    }
    {
        const float4* src4 = (const float4*)(act + b0*(long long)(PNT*IN));
        float4* Ap4 = (float4*)Ap;
        for(int q=tid;q<NB*PNT*IN/4;q+=256) Ap4[q]=src4[q];
    }
    if(tid<NB*PNT) deg[tid]=1;      // self loop
    __syncthreads();

    // Gram per sample: 210 pairs, 4 in flight per warp, packed f32x2 dots
    #pragma unroll
    for(int sb=0; sb<NB; sb++){
        const float* ApS = Ap + sb*(PNT*IN);
        float* G = (float*)(bufA + sb*(PNT*PNT));
        for(int q0 = warp*4; q0 < 210; q0 += 32){
            int ii[4], jj[4]; float accv[4];
            #pragma unroll
            for(int u=0;u<4;u++){
                int q = q0+u; if(q >= 210) q = 0;
                ii[u]=pii[q]; jj[u]=pjj[q];
            }
            #pragma unroll
            for(int u=0;u<4;u++){
                const ulonglong2* ri = (const ulonglong2*)&ApS[ii[u]*IN];
                const ulonglong2* rj = (const ulonglong2*)&ApS[jj[u]*IN];
                ull s0=0ull, s1=0ull;
                #pragma unroll
                for(int c=0;c<IN/128;c++){
                    ulonglong2 av = ri[lane + c*32], bv = rj[lane + c*32];
                    s0 = ffma2(av.x, bv.x, s0);
                    s1 = ffma2(av.y, bv.y, s1);
                }
                accv[u] = (lo2(s0)+hi2(s0)) + (lo2(s1)+hi2(s1));
            }
            #pragma unroll
            for(int u=0;u<4;u++) accv[u]=warp_sum(accv[u]);
            if(lane==0){
                #pragma unroll
                for(int u=0;u<4;u++) if(q0+u<210){
                    G[ii[u]*PNT+jj[u]] = accv[u];
                    G[jj[u]*PNT+ii[u]] = accv[u];
                }
            }
        }
    }
    __syncthreads();

    // stable K-smallest per row from G (exact reference d2 formula)
    if(tid < NB*PNT){
        const int sb = tid / PNT, i = tid % PNT;
        const float* G = (const float*)(bufA + sb*(PNT*PNT));
        const float gii = G[i*PNT+i];
        float row[PNT];
        #pragma unroll
        for(int j=0;j<PNT;j++)
            row[j] = (j==i) ? __int_as_float(0xff800000)
                            : gii + G[j*PNT+j] - 2.f*G[i*PNT+j];
        unsigned used=0;
        #pragma unroll
        for(int k=0;k<KNN+1;k++){
            float best = __int_as_float(0x7f800000); int bj=0;
            #pragma unroll
            for(int j=0;j<PNT;j++){
                if( !((used>>j)&1u) && row[j] < best ){ best=row[j]; bj=j; }
            }
            used |= 1u<<bj;
            if(k>0) knn[tid*KNN + (k-1)] = (unsigned char)bj;  // first = self
        }
    }
    __syncthreads();                        // G dead; bufA becomes NmP

    for(int q=tid;q<NB*PNT*KNN;q+=256){
        int sb = q/(PNT*KNN);
        atomicAdd(&deg[sb*PNT + knn[q]], 1);
    }
    for(int q=tid;q<NB*PNT*PNT;q+=256) bufA[q]=0ull;
    __syncthreads();
    if(tid<NB*PNT) dinv[tid] = rsqrtf((float)deg[tid]);
    __syncthreads();
    for(int q=tid;q<NB*PNT*KNN;q+=256){
        int sb = q/(PNT*KNN), r = q%(PNT*KNN);
        int u = r>>3;                  // source
        int t = knn[q];                // target
        float w = dinv[sb*PNT+t]*dinv[sb*PNT+u];
        bufA[sb*(PNT*PNT) + u*PNT + t] = pack2f(w,w);
    }
    if(tid<NB*PNT){
        int sb = tid/PNT, p = tid%PNT;
        float w = dinv[tid]*dinv[tid];
        bufA[sb*(PNT*PNT) + p*PNT + p] = pack2f(w,w);
    }
    __syncthreads();

    // Xagg[t][f] = sum_s Nm[t][s]*Ap[s][f]; all 256 lanes active (NB*IN/2 == 256)
    {
        const int sb  = tid / (IN/2);        // warp-uniform (IN/2 >= 64)
        const int f2l = tid % (IN/2);
        const float* ApS = Ap + sb*(PNT*IN);
        const ull* NmP = bufA + sb*(PNT*PNT);
        ull acc[PNT];
        #pragma unroll
        for(int t=0;t<PNT;t++) acc[t]=0ull;
        #pragma unroll 2
        for(int s=0;s<PNT;s++){
            ull av = *(const ull*)&ApS[s*IN + 2*f2l];
            const ull* nrow = &NmP[s*PNT];
            #pragma unroll
            for(int t=0;t<PNT;t++) acc[t] = ffma2(av, nrow[t], acc[t]);
        }
        float* dst = outp + (b0+sb)*(long long)(PNT*IN);
        #pragma unroll
        for(int t=0;t<PNT;t++) *(ull*)&dst[t*IN + 2*f2l] = acc[t];
    }
}
#define GRAPH_SMEM(NB) (40960 + (NB)*PNT*PNT*8 + (NB)*PNT*KNN + (NB)*PNT*4 + (NB)*PNT*4 + 512)

// ============================================================================
// head: mean pool -> fc 128x64 relu -> fc 64x3 -> softmax
// ============================================================================
__global__ void __launch_bounds__(128)
head_kernel(const float* __restrict__ act,
            const float* __restrict__ W4, const float* __restrict__ b4,
            const float* __restrict__ W5, const float* __restrict__ b5,
            float* __restrict__ out)
{
    __shared__ float msm[128], hsm[64], lsm[3];
    const int tid = threadIdx.x;
    const long long b = blockIdx.x;
    const float* ab = act + b*(long long)(PNT*128);
    {
        float s=0.f;
        #pragma unroll
        for(int p=0;p<PNT;p++) s += ab[p*128 + tid];
        msm[tid] = s * (1.f/PNT);
    }
    __syncthreads();
    if(tid<64){
        float a=b4[tid];
        #pragma unroll 4
        for(int f=0;f<128;f++) a = fmaf(msm[f], W4[f*64+tid], a);
        hsm[tid]=fmaxf(a,0.f);
    }
    __syncthreads();
    if(tid<3){
        float a=b5[tid];
        #pragma unroll
        for(int j=0;j<64;j++) a = fmaf(hsm[j], W5[j*3+tid], a);
        lsm[tid]=a;
    }
    __syncthreads();
    if(tid==0){
        float l0=lsm[0], l1=lsm[1], l2=lsm[2];
        float m=fmaxf(l0,fmaxf(l1,l2));
        float e0=expf(l0-m), e1=expf(l1-m), e2=expf(l2-m);
        float s=e0+e1+e2;
        out[b*3+0]=e0/s; out[b*3+1]=e1/s; out[b*3+2]=e2/s;
    }
}

extern "C" void kernel_launch(void* const* d_in, const int* in_sizes, int n_in,
                              void* d_out, int out_size){
    const float* x  = (const float*)d_in[0];
    const float* W1 = (const float*)d_in[1];
    const float* b1 = (const float*)d_in[2];
    const float* W2 = (const float*)d_in[3];
    const float* b2 = (const float*)d_in[4];
    const float* W3 = (const float*)d_in[5];
    const float* b3 = (const float*)d_in[6];
    const float* W4 = (const float*)d_in[7];
    const float* b4 = (const float*)d_in[8];
    const float* W5 = (const float*)d_in[9];
    const float* b5 = (const float*)d_in[10];
    float* out = (float*)d_out;

    const int NS = in_sizes[0]/(PNT*D0);   // 8192
    const int M  = NS*PNT;                 // 163840

    float *act, *tmp;
    cudaGetSymbolAddress((void**)&act, g_act);
    cudaGetSymbolAddress((void**)&tmp, g_tmp);

    cudaFuncSetAttribute(graph_kernel<128,4>,
        cudaFuncAttributeMaxDynamicSharedMemorySize, GRAPH_SMEM(4));
    cudaFuncSetAttribute(graph_kernel<256,2>,
        cudaFuncAttributeMaxDynamicSharedMemorySize, GRAPH_SMEM(2));
    cudaFuncSetAttribute(graph_kernel<512,1>,
        cudaFuncAttributeMaxDynamicSharedMemorySize, GRAPH_SMEM(1));

    // layer 1: xagg = Nm@x, then GEMM+bias+relu (aggregate-before)
    graph_kernel<128,4><<<NS/4,256,GRAPH_SMEM(4)>>>(x, tmp);
    sgemm_kernel<true><<<dim3(2, M/128),256>>>(tmp, W1, b1, act, M, 256, 128);
    // layer 2
    graph_kernel<256,2><<<NS/2,256,GRAPH_SMEM(2)>>>(act, tmp);
    sgemm_kernel<true><<<dim3(4, M/128),256>>>(tmp, W2, b2, act, M, 512, 256);
    // layer 3
    graph_kernel<512,1><<<NS,256,GRAPH_SMEM(1)>>>(act, tmp);
    sgemm_kernel<true><<<dim3(1, M/128),256>>>(tmp, W3, b3, act, M, 128, 512);
    // head
    head_kernel<<<NS,128>>>(act, W4, b4, W5, b5, out);
}

// round 14
// speedup vs baseline: 1.1323x; 1.0387x over previous
#include <cuda_runtime.h>
#include <math.h>

#define PNT 20
#define KNN 8
#define D0  128
#define MAXN 8192
typedef unsigned long long ull;

__device__ float g_act[ (size_t)MAXN*PNT*512 ];   // activations (widest 512)
__device__ float g_tmp[ (size_t)MAXN*PNT*512 ];   // xagg scratch (widest 512)

__device__ __forceinline__ ull pack2f(float x, float y){
    return ((ull)__float_as_uint(y) << 32) | (ull)__float_as_uint(x);
}
__device__ __forceinline__ ull ffma2(ull a, ull b, ull c){
    ull d;
    asm("fma.rn.f32x2 %0, %1, %2, %3;" : "=l"(d) : "l"(a), "l"(b), "l"(c));
    return d;
}
__device__ __forceinline__ float lo2(ull v){ return __uint_as_float((unsigned)(v & 0xffffffffull)); }
__device__ __forceinline__ float hi2(ull v){ return __uint_as_float((unsigned)(v >> 32)); }
__device__ __forceinline__ float warp_sum(float v){
    #pragma unroll
    for(int m=16;m>0;m>>=1) v += __shfl_xor_sync(0xffffffffu, v, m);
    return v;
}

// ============================================================================
// sgemm: 128x128x16 tiles, TRIPLE-buffered smem, prefetch distance 2
// (LDG for tile t+2 at block-t start; its STS at end of block t+1 -> ~350cyc
// in flight vs 262cyc L2 latency). Inner loop identical to proven R11 code:
// 8 warps = 4(m) x 2(n), lanes 4(m) x 8(n), conflict-free fragments.
// nk is always even (K in {128,256,512}) -> block pairs, 2 register sets.
// ============================================================================
#define AS_FLOATS (16*132)
#define BS_FLOATS (16*128)
#define SGEMM_SMEM ((3*AS_FLOATS + 3*BS_FLOATS)*4)

__device__ __forceinline__ void gemm_block16(const float* __restrict__ Ab,
                                             const float* __restrict__ Bb,
                                             int mb, int nb, ull (&acc)[4][8]){
    #pragma unroll
    for(int k=0;k<16;k++){
        ulonglong2 a01 = *(const ulonglong2*)&Ab[k*132+mb];
        ulonglong2 a23 = *(const ulonglong2*)&Ab[k*132+mb+16];
        float4 q0 = *(const float4*)&Bb[k*128+nb];
        float4 q1 = *(const float4*)&Bb[k*128+nb+32];
        ull am[4] = {a01.x, a01.y, a23.x, a23.y};
        float bb[8] = {q0.x,q0.y,q0.z,q0.w, q1.x,q1.y,q1.z,q1.w};
        #pragma unroll
        for(int c=0;c<8;c++){
            ull w = pack2f(bb[c], bb[c]);
            #pragma unroll
            for(int r=0;r<4;r++) acc[r][c] = ffma2(am[r], w, acc[r][c]);
        }
    }
}

__device__ __forceinline__ void stage_store(float* __restrict__ Ab, float* __restrict__ Bb,
    int ar, int ac, int br, int bc,
    const float4& a0, const float4& a1, const float4& b0, const float4& b1){
    Ab[(ac+0)*132+ar] = a0.x; Ab[(ac+1)*132+ar] = a0.y;
    Ab[(ac+2)*132+ar] = a0.z; Ab[(ac+3)*132+ar] = a0.w;
    Ab[(ac+0)*132+ar+64] = a1.x; Ab[(ac+1)*132+ar+64] = a1.y;
    Ab[(ac+2)*132+ar+64] = a1.z; Ab[(ac+3)*132+ar+64] = a1.w;
    *(float4*)&Bb[br*128+bc]     = b0;
    *(float4*)&Bb[(br+8)*128+bc] = b1;
}

template<bool EPI>
__global__ void __launch_bounds__(256,2)
sgemm_kernel(const float* __restrict__ A, const float* __restrict__ B,
             const float* __restrict__ bias, float* __restrict__ C,
             int M, int N, int K)
{
    extern __shared__ __align__(16) char sg[];
    float* Asm = (float*)sg;                         // [3][16][132]
    float* Bsm = (float*)(sg + 3*AS_FLOATS*4);       // [3][16][128]

    const int tid = threadIdx.x;
    const int warp = tid >> 5, lane = tid & 31;
    const int wm = warp >> 1, wn = warp & 1;
    const int lm = lane & 3,  ln = lane >> 2;
    const int m0 = blockIdx.y * 128, n0 = blockIdx.x * 128;
    const int ar = tid >> 2, ac = (tid & 3) * 4;
    const int br = tid >> 5, bc = (tid & 31) * 4;

    const float* Ag = A + (long long)(m0 + ar) * K + ac;
    const float* Bg = B + (long long)br * N + (n0 + bc);

    #define LOADT(da0,da1,db0,db1,tt) { \
        const float* Ag2 = Ag + (tt)*16; \
        const float* Bg2 = Bg + (long long)((tt)*16) * N; \
        da0 = *(const float4*)(Ag2); \
        da1 = *(const float4*)(Ag2 + (long long)64 * K); \
        db0 = *(const float4*)(Bg2); \
        db1 = *(const float4*)(Bg2 + (long long)8 * N); }

    const int nk = K >> 4;                 // 8 / 16 / 32 — always even

    float4 xa0,xa1,xb0,xb1;                // set X: tiles t+2 (even blocks load)
    float4 ya0,ya1,yb0,yb1;                // set Y: tiles t+1 / t+3

    // prologue: tile 0 -> stage 0 directly; tile 1 -> regs (set Y)
    {
        float4 p0,p1,p2,p3;
        LOADT(p0,p1,p2,p3, 0);
        stage_store(Asm, Bsm, ar,ac,br,bc, p0,p1,p2,p3);
        LOADT(ya0,ya1,yb0,yb1, 1);
    }
    __syncthreads();

    ull acc[4][8];
    #pragma unroll
    for(int r=0;r<4;r++){
        #pragma unroll
        for(int c=0;c<8;c++) acc[r][c]=0ull;
    }

    const int mb = wm*32 + lm*4;
    const int nb = wn*64 + ln*4;

    for(int t=0;t<nk;t+=2){
        const int s0 = t%3, s1 = (t+1)%3, s2 = (t+2)%3;
        // block t: compute stage s0
        if(t+2<nk) LOADT(xa0,xa1,xb0,xb1, t+2);
        gemm_block16(Asm + s0*AS_FLOATS, Bsm + s0*BS_FLOATS, mb, nb, acc);
        stage_store(Asm + s1*AS_FLOATS, Bsm + s1*BS_FLOATS, ar,ac,br,bc, ya0,ya1,yb0,yb1);
        __syncthreads();
        // block t+1: compute stage s1
        if(t+3<nk) LOADT(ya0,ya1,yb0,yb1, t+3);
        gemm_block16(Asm + s1*AS_FLOATS, Bsm + s1*BS_FLOATS, mb, nb, acc);
        if(t+2<nk) stage_store(Asm + s2*AS_FLOATS, Bsm + s2*BS_FLOATS, ar,ac,br,bc, xa0,xa1,xb0,xb1);
        __syncthreads();
    }
    #undef LOADT

    float bz[8];
    if(EPI){
        float4 q0 = *(const float4*)(bias + n0 + nb);
        float4 q1 = *(const float4*)(bias + n0 + nb + 32);
        bz[0]=q0.x; bz[1]=q0.y; bz[2]=q0.z; bz[3]=q0.w;
        bz[4]=q1.x; bz[5]=q1.y; bz[6]=q1.z; bz[7]=q1.w;
    }
    #pragma unroll
    for(int r=0;r<4;r++){
        const int row_lo = m0 + mb + (r&1)*2 + (r>>1)*16;
        float vl[8], vh[8];
        #pragma unroll
        for(int c=0;c<8;c++){
            float lo = lo2(acc[r][c]), hi = hi2(acc[r][c]);
            if(EPI){ lo = fmaxf(lo + bz[c], 0.f); hi = fmaxf(hi + bz[c], 0.f); }
            vl[c]=lo; vh[c]=hi;
        }
        float* c0 = C + (long long)(row_lo    ) * N + n0 + nb;
        float* c1 = C + (long long)(row_lo + 1) * N + n0 + nb;
        *(float4*)(c0)    = make_float4(vl[0],vl[1],vl[2],vl[3]);
        *(float4*)(c0+32) = make_float4(vl[4],vl[5],vl[6],vl[7]);
        *(float4*)(c1)    = make_float4(vh[0],vh[1],vh[2],vh[3]);
        *(float4*)(c1+32) = make_float4(vh[4],vh[5],vh[6],vh[7]);
    }
}

// ============================================================================
// graph kernel, batched (R13) + vectorized Xagg NmP reads (ulonglong2).
// ============================================================================
template<int IN, int NB>
__global__ void __launch_bounds__(256)
graph_kernel(const float* __restrict__ act, float* __restrict__ outp)
{
    extern __shared__ __align__(16) char gsm[];
    float*          Ap   = (float*)gsm;                          // NB * PNT*IN
    ull*            bufA = (ull*)(gsm + 40960);                  // NB * PNT*PNT (G/NmP)
    unsigned char*  knn  = (unsigned char*)(gsm + 40960 + NB*PNT*PNT*8);
    int*            deg  = (int*)(knn + NB*PNT*KNN);
    float*          dinv = (float*)(deg + NB*PNT);
    unsigned char*  pii  = (unsigned char*)(dinv + NB*PNT);
    unsigned char*  pjj  = pii + 210;

    const int tid = threadIdx.x, warp = tid >> 5, lane = tid & 31;
    const long long b0 = (long long)blockIdx.x * NB;

    if(tid < 210){
        int i=0, rem=tid;
        while(rem >= PNT-i){ rem -= PNT-i; i++; }
        pii[tid]=(unsigned char)i; pjj[tid]=(unsigned char)(i+rem);
    }
    {
        const float4* src4 = (const float4*)(act + b0*(long long)(PNT*IN));
        float4* Ap4 = (float4*)Ap;
        for(int q=tid;q<NB*PNT*IN/4;q+=256) Ap4[q]=src4[q];
    }
    if(tid<NB*PNT) deg[tid]=1;      // self loop
    __syncthreads();

    // Gram per sample: 210 pairs, 4 in flight per warp, packed f32x2 dots
    #pragma unroll
    for(int sb=0; sb<NB; sb++){
        const float* ApS = Ap + sb*(PNT*IN);
        float* G = (float*)(bufA + sb*(PNT*PNT));
        for(int q0 = warp*4; q0 < 210; q0 += 32){
            int ii[4], jj[4]; float accv[4];
            #pragma unroll
            for(int u=0;u<4;u++){
                int q = q0+u; if(q >= 210) q = 0;
                ii[u]=pii[q]; jj[u]=pjj[q];
            }
            #pragma unroll
            for(int u=0;u<4;u++){
                const ulonglong2* ri = (const ulonglong2*)&ApS[ii[u]*IN];
                const ulonglong2* rj = (const ulonglong2*)&ApS[jj[u]*IN];
                ull s0=0ull, s1=0ull;
                #pragma unroll
                for(int c=0;c<IN/128;c++){
                    ulonglong2 av = ri[lane + c*32], bv = rj[lane + c*32];
                    s0 = ffma2(av.x, bv.x, s0);
                    s1 = ffma2(av.y, bv.y, s1);
                }
                accv[u] = (lo2(s0)+hi2(s0)) + (lo2(s1)+hi2(s1));
            }
            #pragma unroll
            for(int u=0;u<4;u++) accv[u]=warp_sum(accv[u]);
            if(lane==0){
                #pragma unroll
                for(int u=0;u<4;u++) if(q0+u<210){
                    G[ii[u]*PNT+jj[u]] = accv[u];
                    G[jj[u]*PNT+ii[u]] = accv[u];
                }
            }
        }
    }
    __syncthreads();

    // stable K-smallest per row from G (exact reference d2 formula)
    if(tid < NB*PNT){
        const int sb = tid / PNT, i = tid % PNT;
        const float* G = (const float*)(bufA + sb*(PNT*PNT));
        const float gii = G[i*PNT+i];
        float row[PNT];
        #pragma unroll
        for(int j=0;j<PNT;j++)
            row[j] = (j==i) ? __int_as_float(0xff800000)
                            : gii + G[j*PNT+j] - 2.f*G[i*PNT+j];
        unsigned used=0;
        #pragma unroll
        for(int k=0;k<KNN+1;k++){
            float best = __int_as_float(0x7f800000); int bj=0;
            #pragma unroll
            for(int j=0;j<PNT;j++){
                if( !((used>>j)&1u) && row[j] < best ){ best=row[j]; bj=j; }
            }
            used |= 1u<<bj;
            if(k>0) knn[tid*KNN + (k-1)] = (unsigned char)bj;  // first = self
        }
    }
    __syncthreads();                        // G dead; bufA becomes NmP

    for(int q=tid;q<NB*PNT*KNN;q+=256){
        int sb = q/(PNT*KNN);
        atomicAdd(&deg[sb*PNT + knn[q]], 1);
    }
    for(int q=tid;q<NB*PNT*PNT;q+=256) bufA[q]=0ull;
    __syncthreads();
    if(tid<NB*PNT) dinv[tid] = rsqrtf((float)deg[tid]);
    __syncthreads();
    for(int q=tid;q<NB*PNT*KNN;q+=256){
        int sb = q/(PNT*KNN), r = q%(PNT*KNN);
        int u = r>>3;                  // source
        int t = knn[q];                // target
        float w = dinv[sb*PNT+t]*dinv[sb*PNT+u];
        bufA[sb*(PNT*PNT) + u*PNT + t] = pack2f(w,w);
    }
    if(tid<NB*PNT){
        int sb = tid/PNT, p = tid%PNT;
        float w = dinv[tid]*dinv[tid];
        bufA[sb*(PNT*PNT) + p*PNT + p] = pack2f(w,w);
    }
    __syncthreads();

    // Xagg[t][f] = sum_s Nm[t][s]*Ap[s][f]; NmP rows read as ulonglong2
    {
        const int sb  = tid / (IN/2);        // warp-uniform (IN/2 >= 64)
        const int f2l = tid % (IN/2);
        const float* ApS = Ap + sb*(PNT*IN);
        const ull* NmP = bufA + sb*(PNT*PNT);
        ull acc[PNT];
        #pragma unroll
        for(int t=0;t<PNT;t++) acc[t]=0ull;
        #pragma unroll 2
        for(int s=0;s<PNT;s++){
            ull av = *(const ull*)&ApS[s*IN + 2*f2l];
            const ulonglong2* nrow2 = (const ulonglong2*)&NmP[s*PNT];
            #pragma unroll
            for(int t2=0;t2<PNT/2;t2++){
                ulonglong2 nv = nrow2[t2];       // broadcast LDS.128
                acc[2*t2  ] = ffma2(av, nv.x, acc[2*t2  ]);
                acc[2*t2+1] = ffma2(av, nv.y, acc[2*t2+1]);
            }
        }
        float* dst = outp + (b0+sb)*(long long)(PNT*IN);
        #pragma unroll
        for(int t=0;t<PNT;t++) *(ull*)&dst[t*IN + 2*f2l] = acc[t];
    }
}
#define GRAPH_SMEM(NB) (40960 + (NB)*PNT*PNT*8 + (NB)*PNT*KNN + (NB)*PNT*4 + (NB)*PNT*4 + 512)

// ============================================================================
// head: mean pool -> fc 128x64 relu -> fc 64x3 -> softmax
// ============================================================================
__global__ void __launch_bounds__(128)
head_kernel(const float* __restrict__ act,
            const float* __restrict__ W4, const float* __restrict__ b4,
            const float* __restrict__ W5, const float* __restrict__ b5,
            float* __restrict__ out)
{
    __shared__ float msm[128], hsm[64], lsm[3];
    const int tid = threadIdx.x;
    const long long b = blockIdx.x;
    const float* ab = act + b*(long long)(PNT*128);
    {
        float s=0.f;
        #pragma unroll
        for(int p=0;p<PNT;p++) s += ab[p*128 + tid];
        msm[tid] = s * (1.f/PNT);
    }
    __syncthreads();
    if(tid<64){
        float a=b4[tid];
        #pragma unroll 4
        for(int f=0;f<128;f++) a = fmaf(msm[f], W4[f*64+tid], a);
        hsm[tid]=fmaxf(a,0.f);
    }
    __syncthreads();
    if(tid<3){
        float a=b5[tid];
        #pragma unroll
        for(int j=0;j<64;j++) a = fmaf(hsm[j], W5[j*3+tid], a);
        lsm[tid]=a;
    }
    __syncthreads();
    if(tid==0){
        float l0=lsm[0], l1=lsm[1], l2=lsm[2];
        float m=fmaxf(l0,fmaxf(l1,l2));
        float e0=expf(l0-m), e1=expf(l1-m), e2=expf(l2-m);
        float s=e0+e1+e2;
        out[b*3+0]=e0/s; out[b*3+1]=e1/s; out[b*3+2]=e2/s;
    }
}

extern "C" void kernel_launch(void* const* d_in, const int* in_sizes, int n_in,
                              void* d_out, int out_size){
    const float* x  = (const float*)d_in[0];
    const float* W1 = (const float*)d_in[1];
    const float* b1 = (const float*)d_in[2];
    const float* W2 = (const float*)d_in[3];
    const float* b2 = (const float*)d_in[4];
    const float* W3 = (const float*)d_in[5];
    const float* b3 = (const float*)d_in[6];
    const float* W4 = (const float*)d_in[7];
    const float* b4 = (const float*)d_in[8];
    const float* W5 = (const float*)d_in[9];
    const float* b5 = (const float*)d_in[10];
    float* out = (float*)d_out;

    const int NS = in_sizes[0]/(PNT*D0);   // 8192
    const int M  = NS*PNT;                 // 163840

    float *act, *tmp;
    cudaGetSymbolAddress((void**)&act, g_act);
    cudaGetSymbolAddress((void**)&tmp, g_tmp);

    cudaFuncSetAttribute(sgemm_kernel<true>,
        cudaFuncAttributeMaxDynamicSharedMemorySize, SGEMM_SMEM);
    cudaFuncSetAttribute(graph_kernel<128,4>,
        cudaFuncAttributeMaxDynamicSharedMemorySize, GRAPH_SMEM(4));
    cudaFuncSetAttribute(graph_kernel<256,2>,
        cudaFuncAttributeMaxDynamicSharedMemorySize, GRAPH_SMEM(2));
    cudaFuncSetAttribute(graph_kernel<512,1>,
        cudaFuncAttributeMaxDynamicSharedMemorySize, GRAPH_SMEM(1));

    // layer 1: xagg = Nm@x, then GEMM+bias+relu (aggregate-before)
    graph_kernel<128,4><<<NS/4,256,GRAPH_SMEM(4)>>>(x, tmp);
    sgemm_kernel<true><<<dim3(2, M/128),256,SGEMM_SMEM>>>(tmp, W1, b1, act, M, 256, 128);
    // layer 2
    graph_kernel<256,2><<<NS/2,256,GRAPH_SMEM(2)>>>(act, tmp);
    sgemm_kernel<true><<<dim3(4, M/128),256,SGEMM_SMEM>>>(tmp, W2, b2, act, M, 512, 256);
    // layer 3
    graph_kernel<512,1><<<NS,256,GRAPH_SMEM(1)>>>(act, tmp);
    sgemm_kernel<true><<<dim3(1, M/128),256,SGEMM_SMEM>>>(tmp, W3, b3, act, M, 128, 512);
    // head
    head_kernel<<<NS,128>>>(act, W4, b4, W5, b5, out);
}